// round 17
// baseline (speedup 1.0000x reference)
#include <cuda_runtime.h>
#include <math.h>

// AttFusion: out[g,c,s] = sum_m softmax_m(<x0,xm>_c / 16) * x[m,c,s]
// x: [28, 256, 8448] fp32; out: [8, 256, 8448] fp32.
//
// R17 = R11 (2-tile pipelined CTAs, templated n, __ldlu/__stwt, per-warp
// softmax, grid x=s-block / y=group) with ONE change: softmax weights live
// in per-warp SMEM instead of registers (read back via conflict-free
// LDS.128 inside the streaming loops). Frees ~20 regs -> 64-reg fit ->
// __launch_bounds__(256,4): 4 CTAs/SM, 32 warps (vs 24), more MLP and
// better DRAM/L2 phase interleave.

#define C_DIM   256
#define S_DIM   8448
#define N_MAX   5
#define NWARPS  8
#define FULL    0xffffffffu

__device__ __constant__ int c_off[8] = {0, 2, 5, 9, 14, 17, 19, 23};
__device__ __constant__ int c_len[8] = {2, 3, 4, 5, 3, 2, 4, 5};

template <int N>
__device__ __forceinline__ void reduce_store(
    float4* p, float (*red)[NWARPS][32], int warp, int lo3, int rowg)
{
#pragma unroll
    for (int m = 0; m < N; m++) {
        p[m].x += __shfl_down_sync(FULL, p[m].x, 16);
        p[m].y += __shfl_down_sync(FULL, p[m].y, 16);
        p[m].z += __shfl_down_sync(FULL, p[m].z, 16);
        p[m].w += __shfl_down_sync(FULL, p[m].w, 16);
        p[m].x += __shfl_down_sync(FULL, p[m].x, 8);
        p[m].y += __shfl_down_sync(FULL, p[m].y, 8);
        p[m].z += __shfl_down_sync(FULL, p[m].z, 8);
        p[m].w += __shfl_down_sync(FULL, p[m].w, 8);
    }
    if (rowg == 0) {
#pragma unroll
        for (int m = 0; m < N; m++)
            *reinterpret_cast<float4*>(&red[m][warp][lo3 * 4]) = p[m];
    }
}

// per-warp redundant softmax: lane = position; weights -> this warp's SMEM
template <int N>
__device__ __forceinline__ void softmax_smem(
    const float (*red)[NWARPS][32], float (*wsm)[32], int lane)
{
    float d[N];
#pragma unroll
    for (int m = 0; m < N; m++) {
        float a = 0.0f;
#pragma unroll
        for (int w = 0; w < NWARPS; w++) a += red[m][w][lane];
        d[m] = a * 0.0625f;                    // 1/sqrt(256)
    }
    float mx = d[0];
#pragma unroll
    for (int m = 1; m < N; m++) mx = fmaxf(mx, d[m]);
    float wl[N], s = 0.0f;
#pragma unroll
    for (int m = 0; m < N; m++) { wl[m] = __expf(d[m] - mx); s += wl[m]; }
    const float inv = 1.0f / s;
#pragma unroll
    for (int m = 0; m < N; m++) wsm[m][lane] = wl[m] * inv;
    __syncwarp();                              // cross-lane smem visibility
}

template <int N>
__device__ __forceinline__ void run_group(
    const float* __restrict__ xg, float* __restrict__ og,
    float (*red0)[NWARPS][32], float (*red1)[NWARPS][32],
    float (*wsm)[32],                           // this warp's weight region
    int s0, int lane, int warp, int lo3, int rowg)
{
    const size_t mstr = (size_t)C_DIM * S_DIM;
    const size_t lpos = (size_t)(warp * 32 + rowg) * S_DIM + s0 + lo3 * 4;
    const float* xb0 = xg + lpos;
    const float* xb1 = xb0 + 32;
    float* ob0 = og + lpos;
    float* ob1 = ob0 + 32;

    // ---- P1(t0): partial dots, 8 channel chunks (DRAM) ----
    float4 p[N];
#pragma unroll
    for (int m = 0; m < N; m++) p[m] = make_float4(0.f, 0.f, 0.f, 0.f);
    {
        const float* ptr = xb0;
#pragma unroll
        for (int kk = 0; kk < 8; kk++) {
            float4 xv[N];
#pragma unroll
            for (int m = 0; m < N; m++)
                xv[m] = *reinterpret_cast<const float4*>(ptr + m * mstr);
#pragma unroll
            for (int m = 0; m < N; m++) {
                p[m].x += xv[0].x * xv[m].x;
                p[m].y += xv[0].y * xv[m].y;
                p[m].z += xv[0].z * xv[m].z;
                p[m].w += xv[0].w * xv[m].w;
            }
            ptr += 4 * S_DIM;
        }
    }
    reduce_store<N>(p, red0, warp, lo3, rowg);
    __syncthreads();

    // prefetch t1 chunk 0 (independent of softmax)
    float4 xn[N];
#pragma unroll
    for (int m = 0; m < N; m++)
        xn[m] = *reinterpret_cast<const float4*>(xb1 + m * mstr);

    softmax_smem<N>(red0, wsm, lane);

    // ---- middle: P2(t0) from L2 interleaved with P1(t1) from DRAM ----
    float4 pn[N];
#pragma unroll
    for (int m = 0; m < N; m++) pn[m] = make_float4(0.f, 0.f, 0.f, 0.f);
    {
        const float* cp = xb0;
        const float* np = xb1;
        float*       op = ob0;
#pragma unroll
        for (int kk = 0; kk < 8; kk++) {
#pragma unroll
            for (int m = 0; m < N; m++) {
                pn[m].x += xn[0].x * xn[m].x;
                pn[m].y += xn[0].y * xn[m].y;
                pn[m].z += xn[0].z * xn[m].z;
                pn[m].w += xn[0].w * xn[m].w;
            }
            float4 xc[N];
#pragma unroll
            for (int m = 0; m < N; m++)
                xc[m] = __ldlu(reinterpret_cast<const float4*>(cp + m * mstr));
            float4 acc = make_float4(0.f, 0.f, 0.f, 0.f);
#pragma unroll
            for (int m = 0; m < N; m++) {
                const float4 w = *reinterpret_cast<const float4*>(&wsm[m][lo3 * 4]);
                acc.x += w.x * xc[m].x;
                acc.y += w.y * xc[m].y;
                acc.z += w.z * xc[m].z;
                acc.w += w.w * xc[m].w;
            }
            __stwt(reinterpret_cast<float4*>(op), acc);
            if (kk < 7) {
                np += 4 * S_DIM;
#pragma unroll
                for (int m = 0; m < N; m++)
                    xn[m] = *reinterpret_cast<const float4*>(np + m * mstr);
            }
            cp += 4 * S_DIM;
            op += 4 * S_DIM;
        }
    }
    reduce_store<N>(pn, red1, warp, lo3, rowg);
    __syncthreads();
    softmax_smem<N>(red1, wsm, lane);          // overwrite with t1 weights

    // ---- P2(t1): weighted sum from L2 ----
    {
        const float* ptr = xb1;
        float* op = ob1;
#pragma unroll
        for (int kk = 0; kk < 8; kk++) {
            float4 xc[N];
#pragma unroll
            for (int m = 0; m < N; m++)
                xc[m] = __ldlu(reinterpret_cast<const float4*>(ptr + m * mstr));
            float4 acc = make_float4(0.f, 0.f, 0.f, 0.f);
#pragma unroll
            for (int m = 0; m < N; m++) {
                const float4 w = *reinterpret_cast<const float4*>(&wsm[m][lo3 * 4]);
                acc.x += w.x * xc[m].x;
                acc.y += w.y * xc[m].y;
                acc.z += w.z * xc[m].z;
                acc.w += w.w * xc[m].w;
            }
            __stwt(reinterpret_cast<float4*>(op), acc);
            ptr += 4 * S_DIM;
            op  += 4 * S_DIM;
        }
    }
}

__global__ __launch_bounds__(256, 4)
void attfusion_kernel(const float* __restrict__ x, float* __restrict__ out) {
    __shared__ float red0[N_MAX][NWARPS][32];     // 5 KB
    __shared__ float red1[N_MAX][NWARPS][32];     // 5 KB
    __shared__ float wsm[NWARPS][N_MAX][32];      // 5 KB per-warp weights

    const int g    = blockIdx.y;                   // R11 grid order
    const int s0   = blockIdx.x * 64;              // two 32-pos tiles
    const int tid  = threadIdx.x;
    const int lane = tid & 31;
    const int warp = tid >> 5;
    const int lo3  = lane & 7;                     // position quad
    const int rowg = lane >> 3;                    // channel sub-row 0..3

    const size_t mstr = (size_t)C_DIM * S_DIM;
    const float* xg = x + (size_t)c_off[g] * mstr;
    float*       og = out + (size_t)g * mstr;

    switch (c_len[g]) {
        case 2: run_group<2>(xg, og, red0, red1, wsm[warp], s0, lane, warp, lo3, rowg); break;
        case 3: run_group<3>(xg, og, red0, red1, wsm[warp], s0, lane, warp, lo3, rowg); break;
        case 4: run_group<4>(xg, og, red0, red1, wsm[warp], s0, lane, warp, lo3, rowg); break;
        default: run_group<5>(xg, og, red0, red1, wsm[warp], s0, lane, warp, lo3, rowg); break;
    }
}

extern "C" void kernel_launch(void* const* d_in, const int* in_sizes, int n_in,
                              void* d_out, int out_size) {
    const float* x = (const float*)d_in[0];
    float* out = (float*)d_out;

    dim3 grid(S_DIM / 64, 8);                      // 132 x 8 = 1056 CTAs
    attfusion_kernel<<<grid, 256>>>(x, out);
}